// round 2
// baseline (speedup 1.0000x reference)
#include <cuda_runtime.h>

// 2x2 Haar inverse reconstruction:
//   x: (32, 4, 512, 512) f32  ->  out: (32, 1, 1024, 1024) f32
// With a,b,c,d = x[n,0..3,h,w]:
//   L0 = R*a + R*b ; L1 = R*a - R*b     (pair {0,1}, row-interleaved)
//   H0 = R*c + R*d ; H1 = R*c - R*d     (pair {2,3})
//   out[n,2h,  2w] = R*L0 + R*H0 ; out[n,2h,  2w+1] = R*L0 - R*H0
//   out[n,2h+1,2w] = R*L1 + R*H1 ; out[n,2h+1,2w+1] = R*L1 - R*H1
//
// Pure streaming: 128MiB in + 128MiB out. Each thread: 4x LDG.128, 4x STG.128.

#define RCONST 0.70710678118654752440f

static constexpr int S = 512;     // input spatial
static constexpr int NIMG = 32;   // batch
static constexpr int WQ = S / 4;  // float4 chunks per row = 128

// One scalar pixel group -> 2x2 output quad.
__device__ __forceinline__ void haar4(float a, float b, float c, float d,
                                      float& o00, float& o01, float& o10, float& o11) {
    float l0 = RCONST * a + RCONST * b;
    float l1 = RCONST * a - RCONST * b;
    float h0 = RCONST * c + RCONST * d;
    float h1 = RCONST * c - RCONST * d;
    o00 = RCONST * l0 + RCONST * h0;   // row 2h,   col 2w
    o01 = RCONST * l0 - RCONST * h0;   // row 2h,   col 2w+1
    o10 = RCONST * l1 + RCONST * h1;   // row 2h+1, col 2w
    o11 = RCONST * l1 - RCONST * h1;   // row 2h+1, col 2w+1
}

__global__ __launch_bounds__(256)
void haar_recon_kernel(const float* __restrict__ x, float* __restrict__ out) {
    // tid layout: [n:5][h:9][wq:7]   total = 32*512*128 = 2,097,152 threads
    unsigned tid = blockIdx.x * 256u + threadIdx.x;
    unsigned wq = tid & (WQ - 1);
    unsigned h  = (tid >> 7) & (S - 1);
    unsigned n  = tid >> 16;

    const size_t chan_stride = (size_t)S * S;           // 262144
    const float4* base = (const float4*)(x + (size_t)n * 4 * chan_stride + (size_t)h * S) + wq;

    // 4 independent 128-bit loads (MLP=4)
    float4 a = base[0];
    float4 b = base[chan_stride / 4];
    float4 c = base[2 * chan_stride / 4];
    float4 d = base[3 * chan_stride / 4];

    float4 r0a, r0b, r1a, r1b;   // row0 cols [8wq,8wq+4), [8wq+4,8wq+8); row1 same
    haar4(a.x, b.x, c.x, d.x, r0a.x, r0a.y, r1a.x, r1a.y);
    haar4(a.y, b.y, c.y, d.y, r0a.z, r0a.w, r1a.z, r1a.w);
    haar4(a.z, b.z, c.z, d.z, r0b.x, r0b.y, r1b.x, r1b.y);
    haar4(a.w, b.w, c.w, d.w, r0b.z, r0b.w, r1b.z, r1b.w);

    // output: (n, 2S, 2S); rows 2h and 2h+1, cols [8*wq, 8*wq+8)
    float4* orow0 = (float4*)(out + ((size_t)n * 2 * S + 2 * h) * (2 * S)) + 2 * wq;
    float4* orow1 = orow0 + (2 * S) / 4;   // next row

    orow0[0] = r0a;
    orow0[1] = r0b;
    orow1[0] = r1a;
    orow1[1] = r1b;
}

extern "C" void kernel_launch(void* const* d_in, const int* in_sizes, int n_in,
                              void* d_out, int out_size) {
    const float* x = (const float*)d_in[0];
    float* out = (float*)d_out;
    // total threads = 32 * 512 * 128 = 2,097,152 -> 8192 blocks of 256
    const unsigned total = NIMG * S * WQ;
    haar_recon_kernel<<<total / 256, 256>>>(x, out);
}